// round 3
// baseline (speedup 1.0000x reference)
#include <cuda_runtime.h>
#include <math.h>

// Problem constants
#define NTOK   16384      // B*S
#define NF     32         // features
#define NH     8          // hidden
#define ND     300        // n_dim_model
#define N2D    600        // 2*D

// Fused weights scratch: [f][j][n], j<8 = W2@Wg rows, j==8 = b2@Wg + bg bias row
__device__ float g_Wf[NF * 9 * N2D];   // 32*5400 floats = 691 KB

// ---------------------------------------------------------------------------
// Kernel A: Wf[f][j][n] = sum_k W2[f][j][k] * Wg[f][k][n]   (j<8)
//           Wf[f][8][n] = sum_k b2[f][k]   * Wg[f][k][n] + bg[f][n]
// grid (32, 9), block 256
// ---------------------------------------------------------------------------
__global__ void fuse_weights_kernel(const float* __restrict__ W2,   // [F,8,300]
                                    const float* __restrict__ b2,   // [F,300]
                                    const float* __restrict__ Wg,   // [F,300,600]
                                    const float* __restrict__ bg)   // [F,600]
{
    int f = blockIdx.x;
    int j = blockIdx.y;  // 0..8
    __shared__ float s_a[ND];
    const float* wgf = Wg + (size_t)f * (ND * N2D);
    for (int k = threadIdx.x; k < ND; k += blockDim.x)
        s_a[k] = (j < 8) ? W2[f * (NH * ND) + j * ND + k] : b2[f * ND + k];
    __syncthreads();
    for (int n = threadIdx.x; n < N2D; n += blockDim.x) {
        float acc = 0.f;
        #pragma unroll 4
        for (int k = 0; k < ND; ++k)
            acc = fmaf(s_a[k], wgf[k * N2D + n], acc);
        if (j == 8) acc += bg[f * N2D + n];
        g_Wf[f * 5400 + j * N2D + n] = acc;
    }
}

// ---------------------------------------------------------------------------
// Kernel B: fully fused VSN forward. 16 tokens/block, 256 threads (8 warps),
// 2 tokens per warp.
// Shared layout (floats):
//   s_pre  [16][256]  : 4096   prescaler outputs (flat order f*8+h)
//   s_h1   [16][256]  : 4096   elu(fc1) per (t,f,k), index t*256+f*8+k
//   s_w    [16][32]   : 512    softmax feature weights
//   s_dyn              : 8192   union: phase1 = fl_fc1_w [256][32]
//                                f-loop = Wf rows (5400) + ln_g (300@5400) + ln_b (300@5700)
// ---------------------------------------------------------------------------
__global__ void __launch_bounds__(256, 2)
vsn_main_kernel(const float* __restrict__ x,        // [NTOK, 32]
                const float* __restrict__ pre_w,    // [32,8]
                const float* __restrict__ pre_b,    // [32,8]
                const float* __restrict__ fc1w,     // [32,8,8]
                const float* __restrict__ fc1b,     // [32,8]
                const float* __restrict__ ln_g,     // [32,300]
                const float* __restrict__ ln_b,     // [32,300]
                const float* __restrict__ fl_fc1_w, // [256,32]
                const float* __restrict__ fl_fc1_b, // [32]
                const float* __restrict__ fl_fc2_w, // [32,32]
                const float* __restrict__ fl_fc2_b, // [32]
                const float* __restrict__ fl_gate_w,// [32,64]
                const float* __restrict__ fl_gate_b,// [64]
                const float* __restrict__ fl_ln_g,  // [32]
                const float* __restrict__ fl_ln_b,  // [32]
                float* __restrict__ out,            // [NTOK,300]
                float* __restrict__ out_w)          // [NTOK,32]
{
    extern __shared__ float smem[];
    float* s_pre = smem;               // 4096
    float* s_h1  = smem + 4096;        // 4096
    float* s_w   = smem + 8192;        // 512
    float* s_dyn = smem + 8704;        // 8192

    const int tid  = threadIdx.x;
    const int lane = tid & 31;
    const int warp = tid >> 5;
    const int token_base = blockIdx.x * 16;

    // ---- Phase 1: prescaler into s_pre, stage fl_fc1_w into s_dyn ----
    for (int idx = tid; idx < 4096; idx += 256) {
        int t = idx >> 8, r = idx & 255, f = r >> 3;
        s_pre[idx] = fmaf(x[(token_base + t) * 32 + f], pre_w[r], pre_b[r]);
    }
    {
        const float4* src = (const float4*)fl_fc1_w;
        float4* dst = (float4*)s_dyn;
        for (int i = tid; i < 2048; i += 256) dst[i] = src[i];
    }
    __syncthreads();

    // ---- Phase 2: h1 = elu(pre @ fc1 + b) for all (t,f,k) ----
    for (int idx = tid; idx < 4096; idx += 256) {
        int t = idx >> 8, r = idx & 255, f = r >> 3, k = r & 7;
        float acc = fc1b[r];
        #pragma unroll
        for (int h = 0; h < 8; ++h)
            acc = fmaf(s_pre[(t << 8) + (f << 3) + h], fc1w[(f << 6) + (h << 3) + k], acc);
        s_h1[idx] = acc > 0.f ? acc : expm1f(acc);
    }

    // ---- Phase 3: flattened GRN + softmax (per-warp, 2 tokens) ----
    const int t0 = warp * 2, t1 = t0 + 1;
    {
        float b1 = fl_fc1_b[lane];
        float a0 = b1, a1 = b1;
        #pragma unroll 4
        for (int i = 0; i < 256; ++i) {
            float w = s_dyn[i * 32 + lane];
            a0 = fmaf(s_pre[(t0 << 8) + i], w, a0);
            a1 = fmaf(s_pre[(t1 << 8) + i], w, a1);
        }
        a0 = a0 > 0.f ? a0 : expm1f(a0);
        a1 = a1 > 0.f ? a1 : expm1f(a1);

        float c0 = fl_fc2_b[lane], c1 = c0;
        #pragma unroll
        for (int j = 0; j < 32; ++j) {
            float w = fl_fc2_w[j * 32 + lane];
            c0 = fmaf(__shfl_sync(0xffffffffu, a0, j), w, c0);
            c1 = fmaf(__shfl_sync(0xffffffffu, a1, j), w, c1);
        }

        float ga0 = fl_gate_b[lane], gb0 = fl_gate_b[lane + 32];
        float ga1 = ga0, gb1 = gb0;
        #pragma unroll
        for (int k = 0; k < 32; ++k) {
            float wa = fl_gate_w[k * 64 + lane];
            float wb = fl_gate_w[k * 64 + lane + 32];
            float v0 = __shfl_sync(0xffffffffu, c0, k);
            float v1 = __shfl_sync(0xffffffffu, c1, k);
            ga0 = fmaf(v0, wa, ga0); gb0 = fmaf(v0, wb, gb0);
            ga1 = fmaf(v1, wa, ga1); gb1 = fmaf(v1, wb, gb1);
        }
        float glu0 = ga0 / (1.f + expf(-gb0));
        float glu1 = ga1 / (1.f + expf(-gb1));

        // interp(flat, 256 -> 32)
        float pos = (float)lane * (255.0f / 31.0f);
        int lo = (int)floorf(pos); if (lo > 255) lo = 255;
        int hi = min(lo + 1, 255);
        float wd = pos - (float)lo;
        float r0 = s_pre[(t0 << 8) + lo] * (1.f - wd) + s_pre[(t0 << 8) + hi] * wd;
        float r1 = s_pre[(t1 << 8) + lo] * (1.f - wd) + s_pre[(t1 << 8) + hi] * wd;

        float y0 = glu0 + r0, y1 = glu1 + r1;
        float s0 = y0, q0 = y0 * y0, s1 = y1, q1 = y1 * y1;
        #pragma unroll
        for (int o = 16; o > 0; o >>= 1) {
            s0 += __shfl_xor_sync(0xffffffffu, s0, o);
            q0 += __shfl_xor_sync(0xffffffffu, q0, o);
            s1 += __shfl_xor_sync(0xffffffffu, s1, o);
            q1 += __shfl_xor_sync(0xffffffffu, q1, o);
        }
        float m0 = s0 * (1.f / 32.f), v0 = q0 * (1.f / 32.f) - m0 * m0;
        float m1 = s1 * (1.f / 32.f), v1 = q1 * (1.f / 32.f) - m1 * m1;
        float wl0 = (y0 - m0) * rsqrtf(v0 + 1e-5f) * fl_ln_g[lane] + fl_ln_b[lane];
        float wl1 = (y1 - m1) * rsqrtf(v1 + 1e-5f) * fl_ln_g[lane] + fl_ln_b[lane];

        float mx0 = wl0, mx1 = wl1;
        #pragma unroll
        for (int o = 16; o > 0; o >>= 1) {
            mx0 = fmaxf(mx0, __shfl_xor_sync(0xffffffffu, mx0, o));
            mx1 = fmaxf(mx1, __shfl_xor_sync(0xffffffffu, mx1, o));
        }
        float e0 = expf(wl0 - mx0), e1 = expf(wl1 - mx1);
        float se0 = e0, se1 = e1;
        #pragma unroll
        for (int o = 16; o > 0; o >>= 1) {
            se0 += __shfl_xor_sync(0xffffffffu, se0, o);
            se1 += __shfl_xor_sync(0xffffffffu, se1, o);
        }
        float w0 = e0 / se0, w1 = e1 / se1;
        s_w[t0 * 32 + lane] = w0;
        s_w[t1 * 32 + lane] = w1;
        out_w[(token_base + t0) * 32 + lane] = w0;
        out_w[(token_base + t1) * 32 + lane] = w1;
    }

    // ---- Precompute interp(8->300) coefficients (same for every feature) ----
    int   lo_m[10];
    float wd_m[10];
    #pragma unroll
    for (int m = 0; m < 10; ++m) {
        int d = lane + 32 * m;
        float pos = (float)d * (7.0f / 299.0f);
        int lo = (int)floorf(pos); if (lo > 7) lo = 7;
        lo_m[m] = lo;
        wd_m[m] = pos - (float)lo;
    }

    float acc0[10], acc1[10];
    #pragma unroll
    for (int m = 0; m < 10; ++m) { acc0[m] = 0.f; acc1[m] = 0.f; }

    // ---- Phase 4: per-feature fused gate + GLU + residual + LN + weighted sum ----
    for (int f = 0; f < NF; ++f) {
        __syncthreads();
        {   // stage Wf (5400 floats, via float4) + ln params (600 floats)
            const float4* src = (const float4*)(g_Wf + f * 5400);
            float4* dst = (float4*)s_dyn;
            for (int i = tid; i < 1350; i += 256) dst[i] = src[i];
            for (int i = tid; i < 300; i += 256) {
                s_dyn[5400 + i] = ln_g[f * 300 + i];
                s_dyn[5700 + i] = ln_b[f * 300 + i];
            }
        }
        __syncthreads();

        float h10[8], h11[8];
        #pragma unroll
        for (int j = 0; j < 8; ++j) {
            h10[j] = s_h1[(t0 << 8) + (f << 3) + j];
            h11[j] = s_h1[(t1 << 8) + (f << 3) + j];
        }

        float y0[10], y1[10];
        float sum0 = 0.f, sq0 = 0.f, sum1 = 0.f, sq1 = 0.f;
        #pragma unroll
        for (int m = 0; m < 10; ++m) {
            int d = lane + 32 * m;
            if (d < 300) {
                float gA0 = s_dyn[4800 + d], gB0 = s_dyn[5100 + d];
                float gA1 = gA0, gB1 = gB0;
                #pragma unroll
                for (int j = 0; j < 8; ++j) {
                    float wA = s_dyn[j * 600 + d];
                    float wB = s_dyn[j * 600 + 300 + d];
                    gA0 = fmaf(h10[j], wA, gA0); gB0 = fmaf(h10[j], wB, gB0);
                    gA1 = fmaf(h11[j], wA, gA1); gB1 = fmaf(h11[j], wB, gB1);
                }
                int lo = lo_m[m], hi = min(lo + 1, 7);
                float wd = wd_m[m];
                float p0l = s_pre[(t0 << 8) + (f << 3) + lo];
                float p0h = s_pre[(t0 << 8) + (f << 3) + hi];
                float p1l = s_pre[(t1 << 8) + (f << 3) + lo];
                float p1h = s_pre[(t1 << 8) + (f << 3) + hi];
                float r0 = p0l * (1.f - wd) + p0h * wd;
                float r1 = p1l * (1.f - wd) + p1h * wd;
                float v0 = gA0 / (1.f + expf(-gB0)) + r0;
                float v1 = gA1 / (1.f + expf(-gB1)) + r1;
                y0[m] = v0; y1[m] = v1;
                sum0 += v0; sq0 += v0 * v0;
                sum1 += v1; sq1 += v1 * v1;
            } else { y0[m] = 0.f; y1[m] = 0.f; }
        }
        #pragma unroll
        for (int o = 16; o > 0; o >>= 1) {
            sum0 += __shfl_xor_sync(0xffffffffu, sum0, o);
            sq0  += __shfl_xor_sync(0xffffffffu, sq0,  o);
            sum1 += __shfl_xor_sync(0xffffffffu, sum1, o);
            sq1  += __shfl_xor_sync(0xffffffffu, sq1,  o);
        }
        float mean0 = sum0 * (1.f / 300.f);
        float var0  = sq0 * (1.f / 300.f) - mean0 * mean0;
        float inv0  = rsqrtf(var0 + 1e-5f);
        float mean1 = sum1 * (1.f / 300.f);
        float var1  = sq1 * (1.f / 300.f) - mean1 * mean1;
        float inv1  = rsqrtf(var1 + 1e-5f);
        float w0 = s_w[t0 * 32 + f], w1 = s_w[t1 * 32 + f];
        #pragma unroll
        for (int m = 0; m < 10; ++m) {
            int d = lane + 32 * m;
            if (d < 300) {
                float lg = s_dyn[5400 + d], lb = s_dyn[5700 + d];
                acc0[m] = fmaf(fmaf(y0[m] - mean0, inv0 * lg, lb), w0, acc0[m]);
                acc1[m] = fmaf(fmaf(y1[m] - mean1, inv1 * lg, lb), w1, acc1[m]);
            }
        }
    }

    #pragma unroll
    for (int m = 0; m < 10; ++m) {
        int d = lane + 32 * m;
        if (d < 300) {
            out[(token_base + t0) * 300 + d] = acc0[m];
            out[(token_base + t1) * 300 + d] = acc1[m];
        }
    }
}

// ---------------------------------------------------------------------------
extern "C" void kernel_launch(void* const* d_in, const int* in_sizes, int n_in,
                              void* d_out, int out_size)
{
    const float* x         = (const float*)d_in[0];
    const float* pre_w     = (const float*)d_in[1];
    const float* pre_b     = (const float*)d_in[2];
    const float* sg_fc1_w  = (const float*)d_in[3];
    const float* sg_fc1_b  = (const float*)d_in[4];
    const float* sg_fc2_w  = (const float*)d_in[5];
    const float* sg_fc2_b  = (const float*)d_in[6];
    const float* sg_gate_w = (const float*)d_in[7];
    const float* sg_gate_b = (const float*)d_in[8];
    const float* sg_ln_g   = (const float*)d_in[9];
    const float* sg_ln_b   = (const float*)d_in[10];
    const float* fl_fc1_w  = (const float*)d_in[11];
    const float* fl_fc1_b  = (const float*)d_in[12];
    const float* fl_fc2_w  = (const float*)d_in[13];
    const float* fl_fc2_b  = (const float*)d_in[14];
    const float* fl_gate_w = (const float*)d_in[15];
    const float* fl_gate_b = (const float*)d_in[16];
    const float* fl_ln_g   = (const float*)d_in[17];
    const float* fl_ln_b   = (const float*)d_in[18];

    float* out   = (float*)d_out;                 // [16384, 300]
    float* out_w = out + (size_t)NTOK * ND;       // [16384, 32]

    fuse_weights_kernel<<<dim3(NF, 9), 256>>>(sg_fc2_w, sg_fc2_b, sg_gate_w, sg_gate_b);

    size_t smem_bytes = (size_t)(4096 + 4096 + 512 + 8192) * sizeof(float); // 67584
    cudaFuncSetAttribute(vsn_main_kernel,
                         cudaFuncAttributeMaxDynamicSharedMemorySize,
                         (int)smem_bytes);
    vsn_main_kernel<<<NTOK / 16, 256, smem_bytes>>>(
        x, pre_w, pre_b, sg_fc1_w, sg_fc1_b, sg_ln_g, sg_ln_b,
        fl_fc1_w, fl_fc1_b, fl_fc2_w, fl_fc2_b, fl_gate_w, fl_gate_b,
        fl_ln_g, fl_ln_b, out, out_w);
}

// round 5
// speedup vs baseline: 1.1609x; 1.1609x over previous
#include <cuda_runtime.h>
#include <math.h>

// Problem constants
#define NTOK   16384      // B*S
#define NF     32         // features
#define NH     8          // hidden
#define ND     300        // n_dim_model
#define N2D    600        // 2*D
#define RECW   20         // floats per d-record

// Packed fused-weight records: [f][d][RECW]
//   slots 0..15 : (wA_j, wB_j) interleaved pairs, j = 0..7   (wA = W2@Wg cols 0..299, wB = cols 300..599)
//   slots 16,17 : fused gate bias pair (gA, gB) = b2@Wg + bg
//   slots 18,19 : ln_g, ln_b
__device__ float g_Wrec[NF * ND * RECW];   // 192000 floats = 768 KB

// ---------------------------------------------------------------------------
// packed f32x2 helpers (sm_100+)
// ---------------------------------------------------------------------------
__device__ __forceinline__ unsigned long long ffma2(unsigned long long a,
                                                    unsigned long long b,
                                                    unsigned long long c) {
    unsigned long long d;
    asm("fma.rn.f32x2 %0, %1, %2, %3;" : "=l"(d) : "l"(a), "l"(b), "l"(c));
    return d;
}
__device__ __forceinline__ unsigned long long pack2(float lo, float hi) {
    unsigned long long r;
    asm("mov.b64 %0, {%1, %2};" : "=l"(r) : "f"(lo), "f"(hi));
    return r;
}
__device__ __forceinline__ void unpack2(unsigned long long v, float& lo, float& hi) {
    asm("mov.b64 {%0, %1}, %2;" : "=f"(lo), "=f"(hi) : "l"(v));
}

// ---------------------------------------------------------------------------
// Kernel A: fuse W2@Wg (+ bias row) and scatter into packed record layout.
// grid (32, 9), block 256
// ---------------------------------------------------------------------------
__global__ void fuse_weights_kernel(const float* __restrict__ W2,   // [F,8,300]
                                    const float* __restrict__ b2,   // [F,300]
                                    const float* __restrict__ Wg,   // [F,300,600]
                                    const float* __restrict__ bg,   // [F,600]
                                    const float* __restrict__ lng,  // [F,300]
                                    const float* __restrict__ lnb)  // [F,300]
{
    int f = blockIdx.x;
    int j = blockIdx.y;  // 0..8 (8 == bias row)
    __shared__ float s_a[ND];
    const float* wgf = Wg + (size_t)f * (ND * N2D);
    for (int k = threadIdx.x; k < ND; k += blockDim.x)
        s_a[k] = (j < 8) ? W2[f * (NH * ND) + j * ND + k] : b2[f * ND + k];
    __syncthreads();
    float* recf = g_Wrec + (size_t)f * (ND * RECW);
    for (int n = threadIdx.x; n < N2D; n += blockDim.x) {
        float acc = 0.f;
        #pragma unroll 4
        for (int k = 0; k < ND; ++k)
            acc = fmaf(s_a[k], wgf[k * N2D + n], acc);
        if (j == 8) acc += bg[f * N2D + n];
        int d  = (n < ND) ? n : (n - ND);
        int hb = (n < ND) ? 0 : 1;
        int slot = (j < 8) ? (2 * j + hb) : (16 + hb);
        recf[d * RECW + slot] = acc;
    }
    if (j == 8) {
        for (int n = threadIdx.x; n < ND; n += blockDim.x) {
            recf[n * RECW + 18] = lng[f * ND + n];
            recf[n * RECW + 19] = lnb[f * ND + n];
        }
    }
}

// ---------------------------------------------------------------------------
// Kernel B: fully fused VSN forward. 16 tokens/block, 256 threads (8 warps),
// 2 tokens per warp.
// Shared layout (floats):
//   s_pre  [16][256]  : 4096
//   s_h1   [16][256]  : 4096
//   s_w    [16][32]   : 512
//   s_dyn             : 8192  (phase1/3: fl_fc1_w [256][32];
//                              f-loop: 6400 = 320 padded d-records of 20 floats)
// ---------------------------------------------------------------------------
__global__ void __launch_bounds__(256, 2)
vsn_main_kernel(const float* __restrict__ x,        // [NTOK, 32]
                const float* __restrict__ pre_w,    // [32,8]
                const float* __restrict__ pre_b,    // [32,8]
                const float* __restrict__ fc1w,     // [32,8,8]
                const float* __restrict__ fc1b,     // [32,8]
                const float* __restrict__ fl_fc1_w, // [256,32]
                const float* __restrict__ fl_fc1_b, // [32]
                const float* __restrict__ fl_fc2_w, // [32,32]
                const float* __restrict__ fl_fc2_b, // [32]
                const float* __restrict__ fl_gate_w,// [32,64]
                const float* __restrict__ fl_gate_b,// [64]
                const float* __restrict__ fl_ln_g,  // [32]
                const float* __restrict__ fl_ln_b,  // [32]
                float* __restrict__ out,            // [NTOK,300]
                float* __restrict__ out_w)          // [NTOK,32]
{
    extern __shared__ float smem[];
    float* s_pre = smem;               // 4096
    float* s_h1  = smem + 4096;        // 4096
    float* s_w   = smem + 8192;        // 512
    float* s_dyn = smem + 8704;        // 8192

    const int tid  = threadIdx.x;
    const int lane = tid & 31;
    const int warp = tid >> 5;
    const int token_base = blockIdx.x * 16;

    // ---- Phase 1: prescaler into s_pre, stage fl_fc1_w into s_dyn ----
    for (int idx = tid; idx < 4096; idx += 256) {
        int t = idx >> 8, r = idx & 255, f = r >> 3;
        s_pre[idx] = fmaf(x[(token_base + t) * 32 + f], pre_w[r], pre_b[r]);
    }
    {
        const float4* src = (const float4*)fl_fc1_w;
        float4* dst = (float4*)s_dyn;
        for (int i = tid; i < 2048; i += 256) dst[i] = src[i];
    }
    __syncthreads();

    // ---- Phase 2: h1 = elu(pre @ fc1 + b) for all (t,f,k) ----
    for (int idx = tid; idx < 4096; idx += 256) {
        int t = idx >> 8, r = idx & 255, f = r >> 3, k = r & 7;
        float acc = fc1b[r];
        #pragma unroll
        for (int h = 0; h < 8; ++h)
            acc = fmaf(s_pre[(t << 8) + (f << 3) + h], fc1w[(f << 6) + (h << 3) + k], acc);
        s_h1[idx] = acc > 0.f ? acc : expm1f(acc);
    }

    // ---- Phase 3: flattened GRN + softmax (per-warp, 2 tokens) ----
    const int t0 = warp * 2, t1 = t0 + 1;
    {
        float b1 = fl_fc1_b[lane];
        float a0 = b1, a1 = b1;
        #pragma unroll 4
        for (int i = 0; i < 256; ++i) {
            float w = s_dyn[i * 32 + lane];
            a0 = fmaf(s_pre[(t0 << 8) + i], w, a0);
            a1 = fmaf(s_pre[(t1 << 8) + i], w, a1);
        }
        a0 = a0 > 0.f ? a0 : expm1f(a0);
        a1 = a1 > 0.f ? a1 : expm1f(a1);

        float c0 = fl_fc2_b[lane], c1 = c0;
        #pragma unroll
        for (int j = 0; j < 32; ++j) {
            float w = fl_fc2_w[j * 32 + lane];
            c0 = fmaf(__shfl_sync(0xffffffffu, a0, j), w, c0);
            c1 = fmaf(__shfl_sync(0xffffffffu, a1, j), w, c1);
        }

        float ga0 = fl_gate_b[lane], gb0 = fl_gate_b[lane + 32];
        float ga1 = ga0, gb1 = gb0;
        #pragma unroll
        for (int k = 0; k < 32; ++k) {
            float wa = fl_gate_w[k * 64 + lane];
            float wb = fl_gate_w[k * 64 + lane + 32];
            float v0 = __shfl_sync(0xffffffffu, c0, k);
            float v1 = __shfl_sync(0xffffffffu, c1, k);
            ga0 = fmaf(v0, wa, ga0); gb0 = fmaf(v0, wb, gb0);
            ga1 = fmaf(v1, wa, ga1); gb1 = fmaf(v1, wb, gb1);
        }
        float glu0 = __fdividef(ga0, 1.f + __expf(-gb0));
        float glu1 = __fdividef(ga1, 1.f + __expf(-gb1));

        // interp(flat, 256 -> 32)
        float pos = (float)lane * (255.0f / 31.0f);
        int lo = (int)floorf(pos); if (lo > 255) lo = 255;
        int hi = min(lo + 1, 255);
        float wd = pos - (float)lo;
        float r0 = s_pre[(t0 << 8) + lo] * (1.f - wd) + s_pre[(t0 << 8) + hi] * wd;
        float r1 = s_pre[(t1 << 8) + lo] * (1.f - wd) + s_pre[(t1 << 8) + hi] * wd;

        float y0 = glu0 + r0, y1 = glu1 + r1;
        float s0 = y0, q0 = y0 * y0, s1 = y1, q1 = y1 * y1;
        #pragma unroll
        for (int o = 16; o > 0; o >>= 1) {
            s0 += __shfl_xor_sync(0xffffffffu, s0, o);
            q0 += __shfl_xor_sync(0xffffffffu, q0, o);
            s1 += __shfl_xor_sync(0xffffffffu, s1, o);
            q1 += __shfl_xor_sync(0xffffffffu, q1, o);
        }
        float m0 = s0 * (1.f / 32.f), v0 = q0 * (1.f / 32.f) - m0 * m0;
        float m1 = s1 * (1.f / 32.f), v1 = q1 * (1.f / 32.f) - m1 * m1;
        float wl0 = (y0 - m0) * rsqrtf(v0 + 1e-5f) * fl_ln_g[lane] + fl_ln_b[lane];
        float wl1 = (y1 - m1) * rsqrtf(v1 + 1e-5f) * fl_ln_g[lane] + fl_ln_b[lane];

        float mx0 = wl0, mx1 = wl1;
        #pragma unroll
        for (int o = 16; o > 0; o >>= 1) {
            mx0 = fmaxf(mx0, __shfl_xor_sync(0xffffffffu, mx0, o));
            mx1 = fmaxf(mx1, __shfl_xor_sync(0xffffffffu, mx1, o));
        }
        float e0 = __expf(wl0 - mx0), e1 = __expf(wl1 - mx1);
        float se0 = e0, se1 = e1;
        #pragma unroll
        for (int o = 16; o > 0; o >>= 1) {
            se0 += __shfl_xor_sync(0xffffffffu, se0, o);
            se1 += __shfl_xor_sync(0xffffffffu, se1, o);
        }
        float w0 = __fdividef(e0, se0), w1 = __fdividef(e1, se1);
        s_w[t0 * 32 + lane] = w0;
        s_w[t1 * 32 + lane] = w1;
        out_w[(token_base + t0) * 32 + lane] = w0;
        out_w[(token_base + t1) * 32 + lane] = w1;
    }

    float acc0[10], acc1[10];
    #pragma unroll
    for (int m = 0; m < 10; ++m) { acc0[m] = 0.f; acc1[m] = 0.f; }

    // ---- Phase 4: per-feature fused gate + GLU + residual + LN + weighted sum
    for (int f = 0; f < NF; ++f) {
        __syncthreads();
        {   // stage 320 padded records (6400 floats); pad region zeroed
            const float4* src = (const float4*)(g_Wrec + (size_t)f * (ND * RECW));
            float4* dst = (float4*)s_dyn;
            float4 z = make_float4(0.f, 0.f, 0.f, 0.f);
            for (int i = tid; i < 1600; i += 256)
                dst[i] = (i < 1500) ? src[i] : z;
        }
        __syncthreads();

        // duplicated h1 multipliers (packed f32x2)
        unsigned long long hd0[8], hd1[8];
        #pragma unroll
        for (int j = 0; j < 8; ++j) {
            float a = s_h1[(t0 << 8) + (f << 3) + j];
            float b = s_h1[(t1 << 8) + (f << 3) + j];
            hd0[j] = pack2(a, a);
            hd1[j] = pack2(b, b);
        }

        float y0[10], y1[10];
        float sum0 = 0.f, sq0 = 0.f, sum1 = 0.f, sq1 = 0.f;
        #pragma unroll
        for (int m = 0; m < 10; ++m) {
            const int d = lane + 32 * m;
            const bool act = (m < 9) || (lane < 12);
            const float* rb = s_dyn + d * RECW;
            const ulonglong2* rq = (const ulonglong2*)rb;
            ulonglong2 qa = rq[0];
            ulonglong2 qb = rq[1];
            ulonglong2 qc = rq[2];
            ulonglong2 qd = rq[3];
            unsigned long long bias = *(const unsigned long long*)(rb + 16);

            unsigned long long A0 = bias, A1 = bias;
            A0 = ffma2(hd0[0], qa.x, A0);  A1 = ffma2(hd1[0], qa.x, A1);
            A0 = ffma2(hd0[1], qa.y, A0);  A1 = ffma2(hd1[1], qa.y, A1);
            A0 = ffma2(hd0[2], qb.x, A0);  A1 = ffma2(hd1[2], qb.x, A1);
            A0 = ffma2(hd0[3], qb.y, A0);  A1 = ffma2(hd1[3], qb.y, A1);
            A0 = ffma2(hd0[4], qc.x, A0);  A1 = ffma2(hd1[4], qc.x, A1);
            A0 = ffma2(hd0[5], qc.y, A0);  A1 = ffma2(hd1[5], qc.y, A1);
            A0 = ffma2(hd0[6], qd.x, A0);  A1 = ffma2(hd1[6], qd.x, A1);
            A0 = ffma2(hd0[7], qd.y, A0);  A1 = ffma2(hd1[7], qd.y, A1);

            if (act) {
                float gA0, gB0, gA1, gB1;
                unpack2(A0, gA0, gB0);
                unpack2(A1, gA1, gB1);

                float pos = (float)d * (7.0f / 299.0f);
                int lo = (int)floorf(pos); if (lo > 7) lo = 7;
                int hi = min(lo + 1, 7);
                float wd = pos - (float)lo;
                float p0l = s_pre[(t0 << 8) + (f << 3) + lo];
                float p0h = s_pre[(t0 << 8) + (f << 3) + hi];
                float p1l = s_pre[(t1 << 8) + (f << 3) + lo];
                float p1h = s_pre[(t1 << 8) + (f << 3) + hi];
                float r0 = p0l * (1.f - wd) + p0h * wd;
                float r1 = p1l * (1.f - wd) + p1h * wd;

                float v0 = __fdividef(gA0, 1.f + __expf(-gB0)) + r0;
                float v1 = __fdividef(gA1, 1.f + __expf(-gB1)) + r1;
                y0[m] = v0; y1[m] = v1;
                sum0 += v0; sq0 += v0 * v0;
                sum1 += v1; sq1 += v1 * v1;
            } else {
                y0[m] = 0.f; y1[m] = 0.f;
            }
        }
        #pragma unroll
        for (int o = 16; o > 0; o >>= 1) {
            sum0 += __shfl_xor_sync(0xffffffffu, sum0, o);
            sq0  += __shfl_xor_sync(0xffffffffu, sq0,  o);
            sum1 += __shfl_xor_sync(0xffffffffu, sum1, o);
            sq1  += __shfl_xor_sync(0xffffffffu, sq1,  o);
        }
        float mean0 = sum0 * (1.f / 300.f);
        float inv0  = rsqrtf(sq0 * (1.f / 300.f) - mean0 * mean0 + 1e-5f);
        float mean1 = sum1 * (1.f / 300.f);
        float inv1  = rsqrtf(sq1 * (1.f / 300.f) - mean1 * mean1 + 1e-5f);
        float w0 = s_w[t0 * 32 + f], w1 = s_w[t1 * 32 + f];
        #pragma unroll
        for (int m = 0; m < 10; ++m) {
            const int d = lane + 32 * m;
            const bool act = (m < 9) || (lane < 12);
            if (act) {
                float2 lnp = *(const float2*)(s_dyn + d * RECW + 18);
                acc0[m] = fmaf(fmaf(y0[m] - mean0, inv0 * lnp.x, lnp.y), w0, acc0[m]);
                acc1[m] = fmaf(fmaf(y1[m] - mean1, inv1 * lnp.x, lnp.y), w1, acc1[m]);
            }
        }
    }

    #pragma unroll
    for (int m = 0; m < 10; ++m) {
        const int d = lane + 32 * m;
        if ((m < 9) || (lane < 12)) {
            out[(token_base + t0) * 300 + d] = acc0[m];
            out[(token_base + t1) * 300 + d] = acc1[m];
        }
    }
}

// ---------------------------------------------------------------------------
extern "C" void kernel_launch(void* const* d_in, const int* in_sizes, int n_in,
                              void* d_out, int out_size)
{
    const float* x         = (const float*)d_in[0];
    const float* pre_w     = (const float*)d_in[1];
    const float* pre_b     = (const float*)d_in[2];
    const float* sg_fc1_w  = (const float*)d_in[3];
    const float* sg_fc1_b  = (const float*)d_in[4];
    const float* sg_fc2_w  = (const float*)d_in[5];
    const float* sg_fc2_b  = (const float*)d_in[6];
    const float* sg_gate_w = (const float*)d_in[7];
    const float* sg_gate_b = (const float*)d_in[8];
    const float* sg_ln_g   = (const float*)d_in[9];
    const float* sg_ln_b   = (const float*)d_in[10];
    const float* fl_fc1_w  = (const float*)d_in[11];
    const float* fl_fc1_b  = (const float*)d_in[12];
    const float* fl_fc2_w  = (const float*)d_in[13];
    const float* fl_fc2_b  = (const float*)d_in[14];
    const float* fl_gate_w = (const float*)d_in[15];
    const float* fl_gate_b = (const float*)d_in[16];
    const float* fl_ln_g   = (const float*)d_in[17];
    const float* fl_ln_b   = (const float*)d_in[18];

    float* out   = (float*)d_out;                 // [16384, 300]
    float* out_w = out + (size_t)NTOK * ND;       // [16384, 32]

    fuse_weights_kernel<<<dim3(NF, 9), 256>>>(sg_fc2_w, sg_fc2_b, sg_gate_w,
                                              sg_gate_b, sg_ln_g, sg_ln_b);

    size_t smem_bytes = (size_t)(4096 + 4096 + 512 + 8192) * sizeof(float); // 67584
    cudaFuncSetAttribute(vsn_main_kernel,
                         cudaFuncAttributeMaxDynamicSharedMemorySize,
                         (int)smem_bytes);
    vsn_main_kernel<<<NTOK / 16, 256, smem_bytes>>>(
        x, pre_w, pre_b, sg_fc1_w, sg_fc1_b,
        fl_fc1_w, fl_fc1_b, fl_fc2_w, fl_fc2_b, fl_gate_w, fl_gate_b,
        fl_ln_g, fl_ln_b, out, out_w);
}